// round 5
// baseline (speedup 1.0000x reference)
#include <cuda_runtime.h>
#include <cstdint>
#include <math.h>

#define NN 100000

// ---------------- scratch ----------------
__device__ float g_Q[(size_t)NN * 128];
__device__ float g_K[(size_t)5 * NN * 128];
__device__ float g_V[(size_t)5 * NN * 128];
__device__ float g_E[(size_t)NN * 20];
__device__ float g_H[(size_t)NN * 128];
__device__ float g_F[(size_t)NN * 512];
__device__ float g_denom[20];

__device__ __forceinline__ uint32_t f2tf(float f) {
    uint32_t u; asm("cvt.rna.tf32.f32 %0, %1;" : "=r"(u) : "f"(f)); return u;
}

__global__ void zero_denoms_kernel() {
    if (threadIdx.x < 20) g_denom[threadIdx.x] = 0.0f;
}

// ---------------- tf32 mma.sync GEMM, 128x128 CTA tile, 4 warps of 64x64 ----
// C[gr, cg] = sum_k A[rowmap(gr), k] * B[k, cg]
// B element (k, c): Bbase + z*BzStride + (c>>5)*HS + k*KS + (c&31)
// epi: 0 plain, 1 bias+relu, 2 bias+resid+LayerNorm
__global__ __launch_bounds__(128, 2)
void tgemm(const float* __restrict__ A, int Astride,
           const int* __restrict__ nbr,
           const float* __restrict__ Bbase, int HS, int KS, int BzStride,
           int kchunks,
           float* __restrict__ C, int Cstride, size_t CzStride,
           int epi,
           const float* __restrict__ bias,
           const float* __restrict__ resid,
           const float* __restrict__ gamma,
           const float* __restrict__ beta)
{
    extern __shared__ uint32_t sm[];
    uint32_t* sA = sm;            // [32][132] k-major tf32 bits
    uint32_t* sB = sm + 32*132;   // [32][132]
    __shared__ int rowg[128];

    const int tid  = threadIdx.x;
    const int wid  = tid >> 5;
    const int lane = tid & 31;
    const int g4   = lane >> 2;   // 0..7
    const int t4   = lane & 3;    // 0..3
    const int z    = blockIdx.z;
    const int cg0  = blockIdx.y * 128;
    const int m0   = blockIdx.x * 128;
    const int m0w  = (wid >> 1) * 64;   // warp m offset (0 or 64)
    const int n0w  = (wid & 1) * 64;    // warp n offset (0 or 64)
    const float* Bp = Bbase + (size_t)z * BzStride;
    float*       Cp = C + (size_t)z * CzStride;

    if (tid < 128) {
        int gr  = m0 + tid;
        int idx = (gr < NN) ? gr : (NN - 1);
        if (nbr != nullptr && z > 0 && gr < NN) idx = nbr[gr * 4 + (z - 1)];
        rowg[tid] = idx;
    }
    __syncthreads();

    float d[4][8][4];
#pragma unroll
    for (int i = 0; i < 4; i++)
#pragma unroll
        for (int j = 0; j < 8; j++)
#pragma unroll
            for (int q = 0; q < 4; q++) d[i][j][q] = 0.0f;

    for (int kc = 0; kc < kchunks; ++kc) {
        const int kg0 = kc * 32;
        // A tile: 128 rows x 32 k -> k-major tf32
#pragma unroll
        for (int p = 0; p < 8; ++p) {
            int idx = tid + p * 128;
            int row = idx >> 3;
            int kq  = (idx & 7) << 2;
            const float* src = A + (size_t)rowg[row] * Astride + kg0 + kq;
            float4 v = *(const float4*)src;
            sA[(kq + 0) * 132 + row] = f2tf(v.x);
            sA[(kq + 1) * 132 + row] = f2tf(v.y);
            sA[(kq + 2) * 132 + row] = f2tf(v.z);
            sA[(kq + 3) * 132 + row] = f2tf(v.w);
        }
        // B tile: 32 k x 128 c
#pragma unroll
        for (int p = 0; p < 8; ++p) {
            int i  = tid + p * 128;
            int kl = i >> 5;
            int c  = (i & 31) << 2;
            int cg = cg0 + c;
            const float* src = Bp + (size_t)(cg >> 5) * HS + (size_t)(kg0 + kl) * KS + (cg & 31);
            float4 v = *(const float4*)src;
            uint4 t = make_uint4(f2tf(v.x), f2tf(v.y), f2tf(v.z), f2tf(v.w));
            *(uint4*)(sB + kl * 132 + c) = t;
        }
        __syncthreads();
#pragma unroll
        for (int ks = 0; ks < 4; ++ks) {
            const int kk = ks * 8;
            uint32_t a[4][4], b[8][2];
#pragma unroll
            for (int mf = 0; mf < 4; ++mf) {
                int r = m0w + mf * 16 + g4;
                a[mf][0] = sA[(kk + t4) * 132 + r];
                a[mf][1] = sA[(kk + t4) * 132 + r + 8];
                a[mf][2] = sA[(kk + 4 + t4) * 132 + r];
                a[mf][3] = sA[(kk + 4 + t4) * 132 + r + 8];
            }
#pragma unroll
            for (int nf = 0; nf < 8; ++nf) {
                int c = n0w + nf * 8 + g4;
                b[nf][0] = sB[(kk + t4) * 132 + c];
                b[nf][1] = sB[(kk + 4 + t4) * 132 + c];
            }
#pragma unroll
            for (int mf = 0; mf < 4; ++mf)
#pragma unroll
                for (int nf = 0; nf < 8; ++nf)
                    asm volatile(
                        "mma.sync.aligned.m16n8k8.row.col.f32.tf32.tf32.f32 "
                        "{%0,%1,%2,%3}, {%4,%5,%6,%7}, {%8,%9}, {%0,%1,%2,%3};"
                        : "+f"(d[mf][nf][0]), "+f"(d[mf][nf][1]),
                          "+f"(d[mf][nf][2]), "+f"(d[mf][nf][3])
                        : "r"(a[mf][0]), "r"(a[mf][1]), "r"(a[mf][2]), "r"(a[mf][3]),
                          "r"(b[nf][0]), "r"(b[nf][1]));
        }
        __syncthreads();
    }

    // ---- stage accumulators into padded smem [128][132] (reuses sA/sB region)
    float* sC = (float*)sm;
#pragma unroll
    for (int mf = 0; mf < 4; ++mf)
#pragma unroll
        for (int nf = 0; nf < 8; ++nf) {
            int row = m0w + mf * 16 + g4;
            int col = n0w + nf * 8 + t4 * 2;
            *(float2*)(sC + row * 132 + col)       = make_float2(d[mf][nf][0], d[mf][nf][1]);
            *(float2*)(sC + (row + 8) * 132 + col) = make_float2(d[mf][nf][2], d[mf][nf][3]);
        }
    __syncthreads();

    if (epi == 2) {
        // bias + resid + row LayerNorm (full row in block: cg0==0, Cstride==128)
        for (int rr = wid; rr < 128; rr += 4) {
            int gr = m0 + rr;
            if (gr >= NN) continue;
            const float* rp = resid + (size_t)gr * 128;
            float v0 = sC[rr * 132 + lane]      + bias[lane]      + rp[lane];
            float v1 = sC[rr * 132 + 32 + lane] + bias[32 + lane] + rp[32 + lane];
            float v2 = sC[rr * 132 + 64 + lane] + bias[64 + lane] + rp[64 + lane];
            float v3 = sC[rr * 132 + 96 + lane] + bias[96 + lane] + rp[96 + lane];
            float s1 = v0 + v1 + v2 + v3;
            float s2 = v0 * v0 + v1 * v1 + v2 * v2 + v3 * v3;
#pragma unroll
            for (int o = 16; o > 0; o >>= 1) {
                s1 += __shfl_xor_sync(0xffffffffu, s1, o);
                s2 += __shfl_xor_sync(0xffffffffu, s2, o);
            }
            float mu  = s1 * (1.0f / 128.0f);
            float var = s2 * (1.0f / 128.0f) - mu * mu;
            float rs  = rsqrtf(var + 1e-5f);
            float* dst = Cp + (size_t)gr * 128;
            dst[lane]      = (v0 - mu) * rs * gamma[lane]      + beta[lane];
            dst[lane + 32] = (v1 - mu) * rs * gamma[lane + 32] + beta[lane + 32];
            dst[lane + 64] = (v2 - mu) * rs * gamma[lane + 64] + beta[lane + 64];
            dst[lane + 96] = (v3 - mu) * rs * gamma[lane + 96] + beta[lane + 96];
        }
    } else {
        // each row covered by 8 threads (i&7); each stores 16 contiguous floats
#pragma unroll
        for (int p = 0; p < 8; ++p) {
            int i   = tid + p * 128;
            int row = i >> 3;
            int q   = (i & 7) << 4;          // col base: 0,16,...,112
            int gr  = m0 + row;
            if (gr >= NN) continue;
#pragma unroll
            for (int h = 0; h < 4; ++h) {
                int c  = q + h * 4;
                float4 v = *(const float4*)(sC + row * 132 + c);
                int cg = cg0 + c;
                if (epi == 1) {
                    v.x = fmaxf(v.x + bias[cg + 0], 0.f);
                    v.y = fmaxf(v.y + bias[cg + 1], 0.f);
                    v.z = fmaxf(v.z + bias[cg + 2], 0.f);
                    v.w = fmaxf(v.w + bias[cg + 3], 0.f);
                }
                *(float4*)(Cp + (size_t)gr * Cstride + cg) = v;
            }
        }
    }
}

// ---------------- logits ----------------
__global__ void logits_kernel() {
    __shared__ float sden[20];
    const int tid = threadIdx.x;
    if (tid < 20) sden[tid] = 0.0f;
    __syncthreads();
    const int n    = blockIdx.x * 8 + (tid >> 5);
    const int lane = tid & 31;
    if (n < NN) {
        const float scale = 0.1767766952966369f;
#pragma unroll
        for (int h = 0; h < 4; h++) {
            float q = g_Q[(size_t)n * 128 + h * 32 + lane];
#pragma unroll
            for (int r = 0; r < 5; r++) {
                float s = q * g_K[((size_t)r * NN + n) * 128 + h * 32 + lane];
#pragma unroll
                for (int o = 16; o > 0; o >>= 1) s += __shfl_xor_sync(0xffffffffu, s, o);
                float e = expf(s * scale);
                if (lane == 0) {
                    g_E[(size_t)n * 20 + h * 5 + r] = e;
                    atomicAdd(&sden[h * 5 + r], e);
                }
            }
        }
    }
    __syncthreads();
    if (tid < 20) atomicAdd(&g_denom[tid], sden[tid]);
}

// ---------------- combine + residual + LN1 ----------------
__global__ void combine_ln1_kernel(const float* __restrict__ x,
                                   const float* __restrict__ g1,
                                   const float* __restrict__ be1) {
    __shared__ float sinv[20];
    const int tid = threadIdx.x;
    if (tid < 20) sinv[tid] = 1.0f / g_denom[tid];
    __syncthreads();
    const int n    = blockIdx.x * 8 + (tid >> 5);
    const int lane = tid & 31;
    if (n >= NN) return;
    float t[4];
    float s1 = 0.0f, s2 = 0.0f;
#pragma unroll
    for (int h = 0; h < 4; h++) {
        float z = 0.0f;
#pragma unroll
        for (int r = 0; r < 5; r++) {
            float p = g_E[(size_t)n * 20 + h * 5 + r] * sinv[h * 5 + r];
            z = fmaf(p, g_V[((size_t)r * NN + n) * 128 + h * 32 + lane], z);
        }
        float v = x[(size_t)n * 128 + h * 32 + lane] + z;
        t[h] = v;
        s1 += v;
        s2 = fmaf(v, v, s2);
    }
#pragma unroll
    for (int o = 16; o > 0; o >>= 1) {
        s1 += __shfl_xor_sync(0xffffffffu, s1, o);
        s2 += __shfl_xor_sync(0xffffffffu, s2, o);
    }
    float mu  = s1 * (1.0f / 128.0f);
    float var = s2 * (1.0f / 128.0f) - mu * mu;
    float rs  = rsqrtf(var + 1e-5f);
#pragma unroll
    for (int h = 0; h < 4; h++) {
        int c = h * 32 + lane;
        g_H[(size_t)n * 128 + c] = (t[h] - mu) * rs * g1[c] + be1[c];
    }
}

// ---------------- launch ----------------
extern "C" void kernel_launch(void* const* d_in, const int* in_sizes, int n_in,
                              void* d_out, int out_size)
{
    const float* x   = (const float*)d_in[0];
    const int*   nbr = (const int*)  d_in[1];
    const float* wq  = (const float*)d_in[2];
    const float* wk  = (const float*)d_in[3];
    const float* wv  = (const float*)d_in[4];
    const float* W1  = (const float*)d_in[5];
    const float* b1  = (const float*)d_in[6];
    const float* W2  = (const float*)d_in[7];
    const float* b2  = (const float*)d_in[8];
    const float* g1  = (const float*)d_in[9];
    const float* be1 = (const float*)d_in[10];
    const float* g2  = (const float*)d_in[11];
    const float* be2 = (const float*)d_in[12];
    float* out = (float*)d_out;

    void *pQ, *pK, *pV, *pH, *pF;
    cudaGetSymbolAddress(&pQ, g_Q);
    cudaGetSymbolAddress(&pK, g_K);
    cudaGetSymbolAddress(&pV, g_V);
    cudaGetSymbolAddress(&pH, g_H);
    cudaGetSymbolAddress(&pF, g_F);

    const size_t SMEMSZ = (size_t)128 * 132 * sizeof(float);   // 67584
    cudaFuncSetAttribute((const void*)tgemm,
                         cudaFuncAttributeMaxDynamicSharedMemorySize, (int)SMEMSZ);

    const int GN = (NN + 127) / 128;   // 782

    zero_denoms_kernel<<<1, 32>>>();

    // Q = x @ Wq
    tgemm<<<dim3(GN, 1, 1), 128, SMEMSZ>>>(
        x, 128, nullptr, wq, 4096, 32, 0, 4,
        (float*)pQ, 128, 0, 0, nullptr, nullptr, nullptr, nullptr);

    // K_r = x_nb[:,r] @ Wk[:,r]
    tgemm<<<dim3(GN, 1, 5), 128, SMEMSZ>>>(
        x, 128, nbr, wk, 20480, 32, 4096, 4,
        (float*)pK, 128, (size_t)NN * 128, 0, nullptr, nullptr, nullptr, nullptr);

    // V_r
    tgemm<<<dim3(GN, 1, 5), 128, SMEMSZ>>>(
        x, 128, nbr, wv, 20480, 32, 4096, 4,
        (float*)pV, 128, (size_t)NN * 128, 0, nullptr, nullptr, nullptr, nullptr);

    logits_kernel<<<NN / 8, 256>>>();
    combine_ln1_kernel<<<NN / 8, 256>>>(x, g1, be1);

    // FFN1: relu(H @ W1 + b1)
    tgemm<<<dim3(GN, 4, 1), 128, SMEMSZ>>>(
        (const float*)pH, 128, nullptr, W1, 32, 512, 0, 4,
        (float*)pF, 512, 0, 1, b1, nullptr, nullptr, nullptr);

    // FFN2 + resid + LN2
    tgemm<<<dim3(GN, 1, 1), 128, SMEMSZ>>>(
        (const float*)pF, 512, nullptr, W2, 32, 128, 0, 16,
        out, 128, 0, 2, b2, (const float*)pH, g2, be2);
}

// round 6
// speedup vs baseline: 1.3114x; 1.3114x over previous
#include <cuda_runtime.h>
#include <cstdint>
#include <math.h>

#define NN 100000

// ---------------- scratch ----------------
__device__ float g_Q[(size_t)NN * 128];
__device__ float g_K[(size_t)5 * NN * 128];
__device__ float g_V[(size_t)5 * NN * 128];
__device__ float g_E[(size_t)NN * 20];
__device__ float g_H[(size_t)NN * 128];
__device__ float g_F[(size_t)NN * 512];
__device__ float g_denom[20];

__device__ __forceinline__ uint32_t f2tf(float f) {
    uint32_t u; asm("cvt.rna.tf32.f32 %0, %1;" : "=r"(u) : "f"(f)); return u;
}
__device__ __forceinline__ uint32_t smem_u32(const void* p) {
    uint32_t a;
    asm("{ .reg .u64 t; cvta.to.shared.u64 t, %1; cvt.u32.u64 %0, t; }" : "=r"(a) : "l"(p));
    return a;
}

__global__ void zero_denoms_kernel() {
    if (threadIdx.x < 20) g_denom[threadIdx.x] = 0.0f;
}

// ---------------- tf32 mma.sync GEMM, 128x128 CTA tile, ldmatrix + swizzle ----
// C[gr, cg] = sum_k A[rowmap(gr), k] * B[k, cg]
// B element (k, c): Bbase + z*BzStride + (c>>5)*HS + k*KS + (c&31)
// epi: 0 plain, 1 bias+relu, 2 bias+resid+LayerNorm
__global__ __launch_bounds__(256, 2)
void tgemm(const float* __restrict__ A, int Astride,
           const int* __restrict__ nbr,
           const float* __restrict__ Bbase, int HS, int KS, int BzStride,
           int kchunks,
           float* __restrict__ C, int Cstride, size_t CzStride,
           int epi,
           const float* __restrict__ bias,
           const float* __restrict__ resid,
           const float* __restrict__ gamma,
           const float* __restrict__ beta)
{
    extern __shared__ uint32_t sm[];
    // byte layout: [0,16384) A tile  (128 rows x 32 tf32, 128B/row, XOR swizzle)
    //              [16384,32768) B tile (128 c-rows x 32 tf32 k, same layout)
    char* smc = (char*)sm;
    const uint32_t sbase = smem_u32(smc);
    __shared__ int rowg[128];

    const int tid  = threadIdx.x;
    const int wid  = tid >> 5;
    const int lane = tid & 31;
    const int z    = blockIdx.z;
    const int cg0  = blockIdx.y * 128;
    const int m0   = blockIdx.x * 128;
    const int m0w  = (wid >> 1) * 32;   // warp m offset
    const int n0w  = (wid & 1) * 64;    // warp n offset
    const float* Bp = Bbase + (size_t)z * BzStride;
    float*       Cp = C + (size_t)z * CzStride;

    if (tid < 128) {
        int gr  = m0 + tid;
        int idx = (gr < NN) ? gr : (NN - 1);
        if (nbr != nullptr && z > 0 && gr < NN) idx = nbr[gr * 4 + (z - 1)];
        rowg[tid] = idx;
    }
    __syncthreads();

    // ldmatrix lane addressing (constant per thread)
    const int lrow = lane & 7;          // row within 8-row matrix
    const int lmat = lane >> 3;         // matrix id 0..3
    // A: mats 0/1 -> k-lo, row +0/+8 ; mats 2/3 -> k-hi, row +0/+8
    const int a_hi = lmat >> 1;
    const int a_roff = (lmat & 1) * 8;
    // B: lanes 0-7: (nf, k-lo), 8-15: (nf, k-hi), 16-23: (nf+1, k-lo), 24-31: (nf+1, k-hi)
    const int b_hi = (lane >> 3) & 1;
    const int b_coff = (lane >> 4) * 8;

    float d[2][8][4];
#pragma unroll
    for (int i = 0; i < 2; i++)
#pragma unroll
        for (int j = 0; j < 8; j++)
#pragma unroll
            for (int q = 0; q < 4; q++) d[i][j][q] = 0.0f;

    for (int kc = 0; kc < kchunks; ++kc) {
        const int kg0 = kc * 32;
        // ---- A tile: rows x k, row-major, swizzled 16B chunks, STS.128 ----
#pragma unroll
        for (int p = 0; p < 4; ++p) {
            int i   = tid + p * 256;
            int row = i >> 3;             // 0..127
            int kq  = (i & 7) << 2;       // 0,4,...,28
            const float* src = A + (size_t)rowg[row] * Astride + kg0 + kq;
            float4 v = *(const float4*)src;
            uint4 t = make_uint4(f2tf(v.x), f2tf(v.y), f2tf(v.z), f2tf(v.w));
            uint32_t off = (uint32_t)row * 128u + (uint32_t)((((kq >> 2) ^ (row & 7))) << 4);
            *(uint4*)(smc + off) = t;
        }
        // ---- B tile: c-rows x k, 4 k-strided loads, STS.128 ----
#pragma unroll
        for (int p = 0; p < 4; ++p) {
            int i  = tid + p * 256;
            int c  = i & 127;
            int k0 = (i >> 7) << 2;       // 0,4,...,28
            int cg = cg0 + c;
            const float* src = Bp + (size_t)(cg >> 5) * HS + (size_t)(kg0 + k0) * KS + (cg & 31);
            uint4 t = make_uint4(f2tf(src[0]), f2tf(src[KS]),
                                 f2tf(src[2 * KS]), f2tf(src[3 * KS]));
            uint32_t off = 16384u + (uint32_t)c * 128u
                         + (uint32_t)((((k0 >> 2) ^ (c & 7))) << 4);
            *(uint4*)(smc + off) = t;
        }
        __syncthreads();
#pragma unroll
        for (int ks = 0; ks < 4; ++ks) {
            uint32_t a[2][4], b[8][2];
            // A fragments: 2 x ldmatrix.x4
#pragma unroll
            for (int mf = 0; mf < 2; ++mf) {
                int r = m0w + mf * 16 + lrow + a_roff;
                uint32_t addr = sbase + (uint32_t)r * 128u
                              + (uint32_t)(((2 * ks + a_hi) ^ lrow) << 4);
                asm volatile("ldmatrix.sync.aligned.m8n8.x4.shared.b16 {%0,%1,%2,%3}, [%4];"
                             : "=r"(a[mf][0]), "=r"(a[mf][1]), "=r"(a[mf][2]), "=r"(a[mf][3])
                             : "r"(addr));
            }
            // B fragments: 4 x ldmatrix.x4 (two nf per issue)
#pragma unroll
            for (int pr = 0; pr < 4; ++pr) {
                int c = n0w + pr * 16 + lrow + b_coff;
                uint32_t addr = sbase + 16384u + (uint32_t)c * 128u
                              + (uint32_t)(((2 * ks + b_hi) ^ (c & 7)) << 4);
                asm volatile("ldmatrix.sync.aligned.m8n8.x4.shared.b16 {%0,%1,%2,%3}, [%4];"
                             : "=r"(b[2*pr][0]), "=r"(b[2*pr][1]),
                               "=r"(b[2*pr+1][0]), "=r"(b[2*pr+1][1])
                             : "r"(addr));
            }
#pragma unroll
            for (int mf = 0; mf < 2; ++mf)
#pragma unroll
                for (int nf = 0; nf < 8; ++nf)
                    asm volatile(
                        "mma.sync.aligned.m16n8k8.row.col.f32.tf32.tf32.f32 "
                        "{%0,%1,%2,%3}, {%4,%5,%6,%7}, {%8,%9}, {%0,%1,%2,%3};"
                        : "+f"(d[mf][nf][0]), "+f"(d[mf][nf][1]),
                          "+f"(d[mf][nf][2]), "+f"(d[mf][nf][3])
                        : "r"(a[mf][0]), "r"(a[mf][1]), "r"(a[mf][2]), "r"(a[mf][3]),
                          "r"(b[nf][0]), "r"(b[nf][1]));
        }
        __syncthreads();
    }

    // ---- stage accumulators into padded smem [128][132] (reuses tile region)
    float* sC = (float*)sm;
    const int g4 = lane >> 2, t4 = lane & 3;
#pragma unroll
    for (int mf = 0; mf < 2; ++mf)
#pragma unroll
        for (int nf = 0; nf < 8; ++nf) {
            int row = m0w + mf * 16 + g4;
            int col = n0w + nf * 8 + t4 * 2;
            *(float2*)(sC + row * 132 + col)       = make_float2(d[mf][nf][0], d[mf][nf][1]);
            *(float2*)(sC + (row + 8) * 132 + col) = make_float2(d[mf][nf][2], d[mf][nf][3]);
        }
    __syncthreads();

    if (epi == 2) {
        // bias + resid + row LayerNorm (full row in block: cg0==0, Cstride==128)
        for (int rr = wid; rr < 128; rr += 8) {
            int gr = m0 + rr;
            if (gr >= NN) continue;
            const float* rp = resid + (size_t)gr * 128;
            float v0 = sC[rr * 132 + lane]      + bias[lane]      + rp[lane];
            float v1 = sC[rr * 132 + 32 + lane] + bias[32 + lane] + rp[32 + lane];
            float v2 = sC[rr * 132 + 64 + lane] + bias[64 + lane] + rp[64 + lane];
            float v3 = sC[rr * 132 + 96 + lane] + bias[96 + lane] + rp[96 + lane];
            float s1 = v0 + v1 + v2 + v3;
            float s2 = v0 * v0 + v1 * v1 + v2 * v2 + v3 * v3;
#pragma unroll
            for (int o = 16; o > 0; o >>= 1) {
                s1 += __shfl_xor_sync(0xffffffffu, s1, o);
                s2 += __shfl_xor_sync(0xffffffffu, s2, o);
            }
            float mu  = s1 * (1.0f / 128.0f);
            float var = s2 * (1.0f / 128.0f) - mu * mu;
            float rs  = rsqrtf(var + 1e-5f);
            float* dst = Cp + (size_t)gr * 128;
            dst[lane]      = (v0 - mu) * rs * gamma[lane]      + beta[lane];
            dst[lane + 32] = (v1 - mu) * rs * gamma[lane + 32] + beta[lane + 32];
            dst[lane + 64] = (v2 - mu) * rs * gamma[lane + 64] + beta[lane + 64];
            dst[lane + 96] = (v3 - mu) * rs * gamma[lane + 96] + beta[lane + 96];
        }
    } else {
        // each row covered by 8 threads; each stores 16 contiguous floats
#pragma unroll
        for (int p = 0; p < 4; ++p) {
            int i   = tid + p * 256;
            int row = i >> 3;
            int q   = (i & 7) << 4;
            int gr  = m0 + row;
            if (gr >= NN) continue;
#pragma unroll
            for (int h = 0; h < 4; ++h) {
                int c  = q + h * 4;
                float4 v = *(const float4*)(sC + row * 132 + c);
                int cg = cg0 + c;
                if (epi == 1) {
                    v.x = fmaxf(v.x + bias[cg + 0], 0.f);
                    v.y = fmaxf(v.y + bias[cg + 1], 0.f);
                    v.z = fmaxf(v.z + bias[cg + 2], 0.f);
                    v.w = fmaxf(v.w + bias[cg + 3], 0.f);
                }
                *(float4*)(Cp + (size_t)gr * Cstride + cg) = v;
            }
        }
    }
}

// ---------------- logits ----------------
__global__ void logits_kernel() {
    __shared__ float sden[20];
    const int tid = threadIdx.x;
    if (tid < 20) sden[tid] = 0.0f;
    __syncthreads();
    const int n    = blockIdx.x * 8 + (tid >> 5);
    const int lane = tid & 31;
    if (n < NN) {
        const float scale = 0.1767766952966369f;
#pragma unroll
        for (int h = 0; h < 4; h++) {
            float q = g_Q[(size_t)n * 128 + h * 32 + lane];
#pragma unroll
            for (int r = 0; r < 5; r++) {
                float s = q * g_K[((size_t)r * NN + n) * 128 + h * 32 + lane];
#pragma unroll
                for (int o = 16; o > 0; o >>= 1) s += __shfl_xor_sync(0xffffffffu, s, o);
                float e = expf(s * scale);
                if (lane == 0) {
                    g_E[(size_t)n * 20 + h * 5 + r] = e;
                    atomicAdd(&sden[h * 5 + r], e);
                }
            }
        }
    }
    __syncthreads();
    if (tid < 20) atomicAdd(&g_denom[tid], sden[tid]);
}

// ---------------- combine + residual + LN1 ----------------
__global__ void combine_ln1_kernel(const float* __restrict__ x,
                                   const float* __restrict__ g1,
                                   const float* __restrict__ be1) {
    __shared__ float sinv[20];
    const int tid = threadIdx.x;
    if (tid < 20) sinv[tid] = 1.0f / g_denom[tid];
    __syncthreads();
    const int n    = blockIdx.x * 8 + (tid >> 5);
    const int lane = tid & 31;
    if (n >= NN) return;
    float t[4];
    float s1 = 0.0f, s2 = 0.0f;
#pragma unroll
    for (int h = 0; h < 4; h++) {
        float z = 0.0f;
#pragma unroll
        for (int r = 0; r < 5; r++) {
            float p = g_E[(size_t)n * 20 + h * 5 + r] * sinv[h * 5 + r];
            z = fmaf(p, g_V[((size_t)r * NN + n) * 128 + h * 32 + lane], z);
        }
        float v = x[(size_t)n * 128 + h * 32 + lane] + z;
        t[h] = v;
        s1 += v;
        s2 = fmaf(v, v, s2);
    }
#pragma unroll
    for (int o = 16; o > 0; o >>= 1) {
        s1 += __shfl_xor_sync(0xffffffffu, s1, o);
        s2 += __shfl_xor_sync(0xffffffffu, s2, o);
    }
    float mu  = s1 * (1.0f / 128.0f);
    float var = s2 * (1.0f / 128.0f) - mu * mu;
    float rs  = rsqrtf(var + 1e-5f);
#pragma unroll
    for (int h = 0; h < 4; h++) {
        int c = h * 32 + lane;
        g_H[(size_t)n * 128 + c] = (t[h] - mu) * rs * g1[c] + be1[c];
    }
}

// ---------------- launch ----------------
extern "C" void kernel_launch(void* const* d_in, const int* in_sizes, int n_in,
                              void* d_out, int out_size)
{
    const float* x   = (const float*)d_in[0];
    const int*   nbr = (const int*)  d_in[1];
    const float* wq  = (const float*)d_in[2];
    const float* wk  = (const float*)d_in[3];
    const float* wv  = (const float*)d_in[4];
    const float* W1  = (const float*)d_in[5];
    const float* b1  = (const float*)d_in[6];
    const float* W2  = (const float*)d_in[7];
    const float* b2  = (const float*)d_in[8];
    const float* g1  = (const float*)d_in[9];
    const float* be1 = (const float*)d_in[10];
    const float* g2  = (const float*)d_in[11];
    const float* be2 = (const float*)d_in[12];
    float* out = (float*)d_out;

    void *pQ, *pK, *pV, *pH, *pF;
    cudaGetSymbolAddress(&pQ, g_Q);
    cudaGetSymbolAddress(&pK, g_K);
    cudaGetSymbolAddress(&pV, g_V);
    cudaGetSymbolAddress(&pH, g_H);
    cudaGetSymbolAddress(&pF, g_F);

    const size_t SMEMSZ = (size_t)128 * 132 * sizeof(float);   // 67584 (epilogue stage)
    cudaFuncSetAttribute((const void*)tgemm,
                         cudaFuncAttributeMaxDynamicSharedMemorySize, (int)SMEMSZ);

    const int GN = (NN + 127) / 128;   // 782

    zero_denoms_kernel<<<1, 32>>>();

    // Q = x @ Wq
    tgemm<<<dim3(GN, 1, 1), 256, SMEMSZ>>>(
        x, 128, nullptr, wq, 4096, 32, 0, 4,
        (float*)pQ, 128, 0, 0, nullptr, nullptr, nullptr, nullptr);

    // K_r = x_nb[:,r] @ Wk[:,r]
    tgemm<<<dim3(GN, 1, 5), 256, SMEMSZ>>>(
        x, 128, nbr, wk, 20480, 32, 4096, 4,
        (float*)pK, 128, (size_t)NN * 128, 0, nullptr, nullptr, nullptr, nullptr);

    // V_r
    tgemm<<<dim3(GN, 1, 5), 256, SMEMSZ>>>(
        x, 128, nbr, wv, 20480, 32, 4096, 4,
        (float*)pV, 128, (size_t)NN * 128, 0, nullptr, nullptr, nullptr, nullptr);

    logits_kernel<<<NN / 8, 256>>>();
    combine_ln1_kernel<<<NN / 8, 256>>>(x, g1, be1);

    // FFN1: relu(H @ W1 + b1)
    tgemm<<<dim3(GN, 4, 1), 256, SMEMSZ>>>(
        (const float*)pH, 128, nullptr, W1, 32, 512, 0, 4,
        (float*)pF, 512, 0, 1, b1, nullptr, nullptr, nullptr);

    // FFN2 + resid + LN2
    tgemm<<<dim3(GN, 1, 1), 256, SMEMSZ>>>(
        (const float*)pF, 512, nullptr, W2, 32, 128, 0, 16,
        out, 128, 0, 2, b2, (const float*)pH, g2, be2);
}

// round 7
// speedup vs baseline: 1.8236x; 1.3905x over previous
#include <cuda_runtime.h>
#include <cstdint>
#include <math.h>

#define NN 100000

// ---------------- scratch ----------------
__device__ float g_X [(size_t)NN * 128];      // tf32-rounded x
__device__ float g_Q [(size_t)NN * 128];
__device__ float g_K [(size_t)5 * NN * 128];
__device__ float g_V [(size_t)5 * NN * 128];
__device__ float g_E [(size_t)NN * 20];
__device__ float g_H [(size_t)NN * 128];      // exact H (residual for FFN2)
__device__ float g_Ht[(size_t)NN * 128];      // tf32-rounded H (GEMM input)
__device__ float g_F [(size_t)NN * 512];      // tf32-rounded FFN intermediate
__device__ float g_WT[311296];                // transposed+rounded weights [c][k]
__device__ float g_denom[20];

__device__ __forceinline__ uint32_t f2tf(float f) {
    uint32_t u; asm("cvt.rna.tf32.f32 %0, %1;" : "=r"(u) : "f"(f)); return u;
}
__device__ __forceinline__ float f2tff(float f) {
    return __uint_as_float(f2tf(f));
}
__device__ __forceinline__ uint32_t smem_u32(const void* p) {
    uint32_t a;
    asm("{ .reg .u64 t; cvta.to.shared.u64 t, %1; cvt.u32.u64 %0, t; }" : "=r"(a) : "l"(p));
    return a;
}
__device__ __forceinline__ void cpa16(uint32_t dst, const void* src) {
    asm volatile("cp.async.ca.shared.global [%0], [%1], 16;" :: "r"(dst), "l"(src));
}

__global__ void zero_denoms_kernel() {
    if (threadIdx.x < 20) g_denom[threadIdx.x] = 0.0f;
}

// round x -> g_X (tf32 rna)
__global__ void round_x_kernel(const float* __restrict__ x) {
    size_t i = ((size_t)blockIdx.x * 256 + threadIdx.x) * 4;
    if (i >= (size_t)NN * 128) return;
    float4 v = *(const float4*)(x + i);
    v.x = f2tff(v.x); v.y = f2tff(v.y); v.z = f2tff(v.z); v.w = f2tff(v.w);
    *(float4*)(g_X + i) = v;
}

// out[z][c][k] = round(in[z*inBz + (c>>5)*HS + k*KS + (c&31)])
__global__ void transpose_w(const float* __restrict__ in, float* __restrict__ out,
                            int HS, int KS, int inBz, int Kb, int Ctot) {
    int z = blockIdx.z;
    int idx = blockIdx.x * 256 + threadIdx.x;
    if (idx >= Ctot * Kb) return;
    int c = idx / Kb, k = idx - c * Kb;
    out[(size_t)z * Ctot * Kb + idx] =
        f2tff(in[(size_t)z * inBz + (size_t)(c >> 5) * HS + (size_t)k * KS + (c & 31)]);
}

// ---------------- tf32 mma.sync GEMM: cp.async pipeline + ldmatrix -----------
// C[gr, cg] = sum_k A[rowmap(gr), k] * BT[cg, k]   (BT K-contiguous, pre-rounded)
// epi: 0 plain, 1 bias+relu+round, 2 bias+resid+LayerNorm
__global__ __launch_bounds__(256, 2)
void tgemm(const float* __restrict__ A, int Astride,
           const int* __restrict__ nbr,
           const float* __restrict__ BT, int Kb, size_t BzStride,
           int kchunks,
           float* __restrict__ C, int Cstride, size_t CzStride,
           int epi,
           const float* __restrict__ bias,
           const float* __restrict__ resid,
           const float* __restrict__ gamma,
           const float* __restrict__ beta)
{
    extern __shared__ uint32_t sm[];
    // mainloop: bufA[2] at 0,16384 ; bufB[2] at 32768,49152 (bytes)
    char* smc = (char*)sm;
    const uint32_t sbase = smem_u32(smc);
    __shared__ int rowg[128];

    const int tid  = threadIdx.x;
    const int wid  = tid >> 5;
    const int lane = tid & 31;
    const int z    = blockIdx.z;
    const int cg0  = blockIdx.y * 128;
    const int m0   = blockIdx.x * 128;
    const int m0w  = (wid >> 1) * 32;
    const int n0w  = (wid & 1) * 64;
    const float* Bz = BT + (size_t)z * BzStride;
    float*       Cp = C + (size_t)z * CzStride;

    if (tid < 128) {
        int gr  = m0 + tid;
        int idx = (gr < NN) ? gr : (NN - 1);
        if (nbr != nullptr && z > 0 && gr < NN) idx = nbr[gr * 4 + (z - 1)];
        rowg[tid] = idx;
    }
    __syncthreads();

    // per-thread staging coords (4 iters x 256 threads covers 128 rows x 8 chunks)
    const int srow = tid >> 3;            // + p*32
    const int schk = tid & 7;             // 16B chunk 0..7

    // ldmatrix lane addressing
    const int lrow = lane & 7;
    const int a_hi   = (lane >> 3) >> 1;
    const int a_roff = ((lane >> 3) & 1) * 8;
    const int b_hi   = (lane >> 3) & 1;
    const int b_coff = (lane >> 4) * 8;

    float d[2][8][4];
#pragma unroll
    for (int i = 0; i < 2; i++)
#pragma unroll
        for (int j = 0; j < 8; j++)
#pragma unroll
            for (int q = 0; q < 4; q++) d[i][j][q] = 0.0f;

    // ---- async stage of one chunk into buffer bsel
    auto stage = [&](int bsel, int kc) {
        const int kg0 = kc * 32;
        uint32_t abase = sbase + (uint32_t)bsel * 16384u;
        uint32_t bbase = sbase + 32768u + (uint32_t)bsel * 16384u;
#pragma unroll
        for (int p = 0; p < 4; ++p) {
            int row = srow + p * 32;
            uint32_t off = (uint32_t)row * 128u + (uint32_t)((schk ^ (row & 7)) << 4);
            cpa16(abase + off,
                  A + (size_t)rowg[row] * Astride + kg0 + schk * 4);
            cpa16(bbase + off,
                  Bz + (size_t)(cg0 + row) * Kb + kg0 + schk * 4);
        }
        asm volatile("cp.async.commit_group;" ::: "memory");
    };

    stage(0, 0);

    for (int kc = 0; kc < kchunks; ++kc) {
        const int bsel = kc & 1;
        if (kc + 1 < kchunks) {
            stage(bsel ^ 1, kc + 1);
            asm volatile("cp.async.wait_group 1;" ::: "memory");
        } else {
            asm volatile("cp.async.wait_group 0;" ::: "memory");
        }
        __syncthreads();

        const uint32_t abase = sbase + (uint32_t)bsel * 16384u;
        const uint32_t bbase = sbase + 32768u + (uint32_t)bsel * 16384u;
#pragma unroll
        for (int ks = 0; ks < 4; ++ks) {
            uint32_t a[2][4], b[8][2];
#pragma unroll
            for (int mf = 0; mf < 2; ++mf) {
                int r = m0w + mf * 16 + lrow + a_roff;
                uint32_t addr = abase + (uint32_t)r * 128u
                              + (uint32_t)(((2 * ks + a_hi) ^ lrow) << 4);
                asm volatile("ldmatrix.sync.aligned.m8n8.x4.shared.b16 {%0,%1,%2,%3}, [%4];"
                             : "=r"(a[mf][0]), "=r"(a[mf][1]), "=r"(a[mf][2]), "=r"(a[mf][3])
                             : "r"(addr));
            }
#pragma unroll
            for (int pr = 0; pr < 4; ++pr) {
                int c = n0w + pr * 16 + lrow + b_coff;
                uint32_t addr = bbase + (uint32_t)c * 128u
                              + (uint32_t)(((2 * ks + b_hi) ^ (c & 7)) << 4);
                asm volatile("ldmatrix.sync.aligned.m8n8.x4.shared.b16 {%0,%1,%2,%3}, [%4];"
                             : "=r"(b[2*pr][0]), "=r"(b[2*pr][1]),
                               "=r"(b[2*pr+1][0]), "=r"(b[2*pr+1][1])
                             : "r"(addr));
            }
#pragma unroll
            for (int mf = 0; mf < 2; ++mf)
#pragma unroll
                for (int nf = 0; nf < 8; ++nf)
                    asm volatile(
                        "mma.sync.aligned.m16n8k8.row.col.f32.tf32.tf32.f32 "
                        "{%0,%1,%2,%3}, {%4,%5,%6,%7}, {%8,%9}, {%0,%1,%2,%3};"
                        : "+f"(d[mf][nf][0]), "+f"(d[mf][nf][1]),
                          "+f"(d[mf][nf][2]), "+f"(d[mf][nf][3])
                        : "r"(a[mf][0]), "r"(a[mf][1]), "r"(a[mf][2]), "r"(a[mf][3]),
                          "r"(b[nf][0]), "r"(b[nf][1]));
        }
        __syncthreads();
    }

    // ---- stage accumulators into padded smem [128][132] (reuses tile region)
    float* sC = (float*)sm;
    const int g4 = lane >> 2, t4 = lane & 3;
#pragma unroll
    for (int mf = 0; mf < 2; ++mf)
#pragma unroll
        for (int nf = 0; nf < 8; ++nf) {
            int row = m0w + mf * 16 + g4;
            int col = n0w + nf * 8 + t4 * 2;
            *(float2*)(sC + row * 132 + col)       = make_float2(d[mf][nf][0], d[mf][nf][1]);
            *(float2*)(sC + (row + 8) * 132 + col) = make_float2(d[mf][nf][2], d[mf][nf][3]);
        }
    __syncthreads();

    if (epi == 2) {
        for (int rr = wid; rr < 128; rr += 8) {
            int gr = m0 + rr;
            if (gr >= NN) continue;
            const float* rp = resid + (size_t)gr * 128;
            float v0 = sC[rr * 132 + lane]      + bias[lane]      + rp[lane];
            float v1 = sC[rr * 132 + 32 + lane] + bias[32 + lane] + rp[32 + lane];
            float v2 = sC[rr * 132 + 64 + lane] + bias[64 + lane] + rp[64 + lane];
            float v3 = sC[rr * 132 + 96 + lane] + bias[96 + lane] + rp[96 + lane];
            float s1 = v0 + v1 + v2 + v3;
            float s2 = v0 * v0 + v1 * v1 + v2 * v2 + v3 * v3;
#pragma unroll
            for (int o = 16; o > 0; o >>= 1) {
                s1 += __shfl_xor_sync(0xffffffffu, s1, o);
                s2 += __shfl_xor_sync(0xffffffffu, s2, o);
            }
            float mu  = s1 * (1.0f / 128.0f);
            float var = s2 * (1.0f / 128.0f) - mu * mu;
            float rs  = rsqrtf(var + 1e-5f);
            float* dst = Cp + (size_t)gr * 128;
            dst[lane]      = (v0 - mu) * rs * gamma[lane]      + beta[lane];
            dst[lane + 32] = (v1 - mu) * rs * gamma[lane + 32] + beta[lane + 32];
            dst[lane + 64] = (v2 - mu) * rs * gamma[lane + 64] + beta[lane + 64];
            dst[lane + 96] = (v3 - mu) * rs * gamma[lane + 96] + beta[lane + 96];
        }
    } else {
#pragma unroll
        for (int p = 0; p < 4; ++p) {
            int i   = tid + p * 256;
            int row = i >> 3;
            int q   = (i & 7) << 4;
            int gr  = m0 + row;
            if (gr >= NN) continue;
#pragma unroll
            for (int h = 0; h < 4; ++h) {
                int c  = q + h * 4;
                float4 v = *(const float4*)(sC + row * 132 + c);
                int cg = cg0 + c;
                if (epi == 1) {
                    v.x = f2tff(fmaxf(v.x + bias[cg + 0], 0.f));
                    v.y = f2tff(fmaxf(v.y + bias[cg + 1], 0.f));
                    v.z = f2tff(fmaxf(v.z + bias[cg + 2], 0.f));
                    v.w = f2tff(fmaxf(v.w + bias[cg + 3], 0.f));
                }
                *(float4*)(Cp + (size_t)gr * Cstride + cg) = v;
            }
        }
    }
}

// ---------------- logits ----------------
__global__ void logits_kernel() {
    __shared__ float sden[20];
    const int tid = threadIdx.x;
    if (tid < 20) sden[tid] = 0.0f;
    __syncthreads();
    const int n    = blockIdx.x * 8 + (tid >> 5);
    const int lane = tid & 31;
    if (n < NN) {
        const float scale = 0.1767766952966369f;
#pragma unroll
        for (int h = 0; h < 4; h++) {
            float q = g_Q[(size_t)n * 128 + h * 32 + lane];
#pragma unroll
            for (int r = 0; r < 5; r++) {
                float s = q * g_K[((size_t)r * NN + n) * 128 + h * 32 + lane];
#pragma unroll
                for (int o = 16; o > 0; o >>= 1) s += __shfl_xor_sync(0xffffffffu, s, o);
                float e = expf(s * scale);
                if (lane == 0) {
                    g_E[(size_t)n * 20 + h * 5 + r] = e;
                    atomicAdd(&sden[h * 5 + r], e);
                }
            }
        }
    }
    __syncthreads();
    if (tid < 20) atomicAdd(&g_denom[tid], sden[tid]);
}

// ---------------- combine + residual + LN1 (writes exact H and rounded Ht) ----
__global__ void combine_ln1_kernel(const float* __restrict__ x,
                                   const float* __restrict__ g1,
                                   const float* __restrict__ be1) {
    __shared__ float sinv[20];
    const int tid = threadIdx.x;
    if (tid < 20) sinv[tid] = 1.0f / g_denom[tid];
    __syncthreads();
    const int n    = blockIdx.x * 8 + (tid >> 5);
    const int lane = tid & 31;
    if (n >= NN) return;
    float t[4];
    float s1 = 0.0f, s2 = 0.0f;
#pragma unroll
    for (int h = 0; h < 4; h++) {
        float z = 0.0f;
#pragma unroll
        for (int r = 0; r < 5; r++) {
            float p = g_E[(size_t)n * 20 + h * 5 + r] * sinv[h * 5 + r];
            z = fmaf(p, g_V[((size_t)r * NN + n) * 128 + h * 32 + lane], z);
        }
        float v = x[(size_t)n * 128 + h * 32 + lane] + z;
        t[h] = v;
        s1 += v;
        s2 = fmaf(v, v, s2);
    }
#pragma unroll
    for (int o = 16; o > 0; o >>= 1) {
        s1 += __shfl_xor_sync(0xffffffffu, s1, o);
        s2 += __shfl_xor_sync(0xffffffffu, s2, o);
    }
    float mu  = s1 * (1.0f / 128.0f);
    float var = s2 * (1.0f / 128.0f) - mu * mu;
    float rs  = rsqrtf(var + 1e-5f);
#pragma unroll
    for (int h = 0; h < 4; h++) {
        int c = h * 32 + lane;
        float hv = (t[h] - mu) * rs * g1[c] + be1[c];
        g_H [(size_t)n * 128 + c] = hv;
        g_Ht[(size_t)n * 128 + c] = f2tff(hv);
    }
}

// ---------------- launch ----------------
extern "C" void kernel_launch(void* const* d_in, const int* in_sizes, int n_in,
                              void* d_out, int out_size)
{
    const float* x   = (const float*)d_in[0];
    const int*   nbr = (const int*)  d_in[1];
    const float* wq  = (const float*)d_in[2];
    const float* wk  = (const float*)d_in[3];
    const float* wv  = (const float*)d_in[4];
    const float* W1  = (const float*)d_in[5];
    const float* b1  = (const float*)d_in[6];
    const float* W2  = (const float*)d_in[7];
    const float* b2  = (const float*)d_in[8];
    const float* g1  = (const float*)d_in[9];
    const float* be1 = (const float*)d_in[10];
    const float* g2  = (const float*)d_in[11];
    const float* be2 = (const float*)d_in[12];
    float* out = (float*)d_out;

    void *pX, *pQ, *pK, *pV, *pH, *pHt, *pF, *pW;
    cudaGetSymbolAddress(&pX, g_X);
    cudaGetSymbolAddress(&pQ, g_Q);
    cudaGetSymbolAddress(&pK, g_K);
    cudaGetSymbolAddress(&pV, g_V);
    cudaGetSymbolAddress(&pH, g_H);
    cudaGetSymbolAddress(&pHt, g_Ht);
    cudaGetSymbolAddress(&pF, g_F);
    cudaGetSymbolAddress(&pW, g_WT);
    float* WT = (float*)pW;

    const size_t SMEMSZ = (size_t)128 * 132 * sizeof(float);   // 67584 >= 64KB mainloop
    cudaFuncSetAttribute((const void*)tgemm,
                         cudaFuncAttributeMaxDynamicSharedMemorySize, (int)SMEMSZ);

    const int GN = (NN + 127) / 128;   // 782

    zero_denoms_kernel<<<1, 32>>>();
    round_x_kernel<<<12500, 256>>>(x);

    // transposed + rounded weights (K-contiguous [c][k])
    transpose_w<<<dim3(64, 1, 1),  256>>>(wq, WT + 0,      4096, 32, 0,    128, 128);
    transpose_w<<<dim3(64, 1, 5),  256>>>(wk, WT + 16384,  20480, 32, 4096, 128, 128);
    transpose_w<<<dim3(64, 1, 5),  256>>>(wv, WT + 98304,  20480, 32, 4096, 128, 128);
    transpose_w<<<dim3(256, 1, 1), 256>>>(W1, WT + 180224, 32, 512, 0,    128, 512);
    transpose_w<<<dim3(256, 1, 1), 256>>>(W2, WT + 245760, 32, 128, 0,    512, 128);

    // Q = X @ Wq
    tgemm<<<dim3(GN, 1, 1), 256, SMEMSZ>>>(
        (const float*)pX, 128, nullptr, WT, 128, 0, 4,
        (float*)pQ, 128, 0, 0, nullptr, nullptr, nullptr, nullptr);

    // K_r = X_nb[:,r] @ Wk[:,r]
    tgemm<<<dim3(GN, 1, 5), 256, SMEMSZ>>>(
        (const float*)pX, 128, nbr, WT + 16384, 128, 16384, 4,
        (float*)pK, 128, (size_t)NN * 128, 0, nullptr, nullptr, nullptr, nullptr);

    // V_r
    tgemm<<<dim3(GN, 1, 5), 256, SMEMSZ>>>(
        (const float*)pX, 128, nbr, WT + 98304, 128, 16384, 4,
        (float*)pV, 128, (size_t)NN * 128, 0, nullptr, nullptr, nullptr, nullptr);

    logits_kernel<<<NN / 8, 256>>>();
    combine_ln1_kernel<<<NN / 8, 256>>>(x, g1, be1);

    // FFN1: relu(Ht @ W1 + b1) -> F (rounded)
    tgemm<<<dim3(GN, 4, 1), 256, SMEMSZ>>>(
        (const float*)pHt, 128, nullptr, WT + 180224, 128, 0, 4,
        (float*)pF, 512, 0, 1, b1, nullptr, nullptr, nullptr);

    // FFN2 + resid(H exact) + LN2
    tgemm<<<dim3(GN, 1, 1), 256, SMEMSZ>>>(
        (const float*)pF, 512, nullptr, WT + 245760, 512, 0, 16,
        out, 128, 0, 2, b2, (const float*)pH, g2, be2);
}